// round 2
// baseline (speedup 1.0000x reference)
#include <cuda_runtime.h>

// GRU-D with diagonal weights: each (b,f) pair is an independent length-T
// scalar recurrence. One thread per (b,f); block = one batch row (256 feats);
// fused classifier via warp-shuffle reduction.
//
// Shapes (fixed): B=128, T=1024, F=256, OUT=2.
// input: (B, 3, T, F) float32  -> channel 0 = X, 1 = M, 2 = D (unused).

#define BB   128
#define TT   1024
#define FF   256
#define UNR  8

__device__ __forceinline__ float tanh_fast(float x) {
    float y;
    asm("tanh.approx.f32 %0, %1;" : "=f"(y) : "f"(x));
    return y;
}

__global__ __launch_bounds__(FF, 1)
void grud_kernel(const float* __restrict__ input,
                 const float* __restrict__ x_mean,
                 const float* __restrict__ w_xz, const float* __restrict__ w_hz,
                 const float* __restrict__ w_mz,
                 const float* __restrict__ w_xr, const float* __restrict__ w_hr,
                 const float* __restrict__ w_mr,
                 const float* __restrict__ w_xh, const float* __restrict__ w_hh,
                 const float* __restrict__ w_mh,
                 const float* __restrict__ b_z,  const float* __restrict__ b_r,
                 const float* __restrict__ b_h,
                 const float* __restrict__ W_cls, const float* __restrict__ b_cls,
                 float* __restrict__ out)
{
    const int b = blockIdx.x;
    const int f = threadIdx.x;

    // Per-feature constants. 0.5x-scaled copies implement
    // sigmoid(y) = 0.5*tanh(0.5*y) + 0.5 with no extra ops on the chain.
    const float xm   = x_mean[f];
    const float hwxz = 0.5f * w_xz[f], hwmz = 0.5f * w_mz[f];
    const float hbz  = 0.5f * b_z[f],  hwhz = 0.5f * w_hz[f];
    const float hwxr = 0.5f * w_xr[f], hwmr = 0.5f * w_mr[f];
    const float hbr  = 0.5f * b_r[f],  hwhr = 0.5f * w_hr[f];
    const float wxh  = w_xh[f], wmh = w_mh[f], bh = b_h[f];
    const float hwhh = 0.5f * w_hh[f];

    const float* xp = input + (size_t)b * 3 * TT * FF + f;   // X[b, t, f]
    const float* mp = xp + (size_t)TT * FF;                  // M[b, t, f]

    float h = 0.0f;

    // Double-buffered register prefetch: UNR timesteps per chunk.
    float xb[2][UNR], mb[2][UNR];
    #pragma unroll
    for (int u = 0; u < UNR; u++) {
        xb[0][u] = xp[u * FF];
        mb[0][u] = mp[u * FF];
    }
    xp += UNR * FF; mp += UNR * FF;

    int buf = 0;
    for (int t = 0; t < TT; t += UNR) {
        const int nb = buf ^ 1;
        if (t + UNR < TT) {
            #pragma unroll
            for (int u = 0; u < UNR; u++) {
                xb[nb][u] = xp[u * FF];
                mb[nb][u] = mp[u * FF];
            }
            xp += UNR * FF; mp += UNR * FF;
        }
        #pragma unroll
        for (int u = 0; u < UNR; u++) {
            const float x = xb[buf][u];
            const float m = mb[buf][u];
            // Imputation: m*x + (1-m)*x_mean == fma(m, x - xm, xm)
            const float xi  = fmaf(m, x - xm, xm);
            // h-independent pre-activations (off the critical chain)
            const float azh = fmaf(hwxz, xi, fmaf(hwmz, m, hbz));
            const float arh = fmaf(hwxr, xi, fmaf(hwmr, m, hbr));
            const float ah  = fmaf(wxh,  xi, fmaf(wmh,  m, bh ));
            const float g   = hwhh * h;                 // 0.5*w_hh*h
            // gates via HW tanh
            const float tz  = tanh_fast(fmaf(hwhz, h, azh));
            const float tr  = tanh_fast(fmaf(hwhr, h, arh));
            const float z   = fmaf(0.5f, tz, 0.5f);
            // w_hh*(r*h) = g*tr + g  since r = 0.5*tr + 0.5
            const float uu  = fmaf(g, tr, g + ah);
            const float th  = tanh_fast(uu);            // h_tilde
            h = fmaf(z, th - h, h);                     // (1-z)h + z*h~
        }
        buf = nb;
    }

    // Fused classifier: out[b, o] = sigmoid(sum_f h*W_cls[o,f] + b_cls[o])
    // Warp-shuffle partial reduce, then combine 8 warp sums in smem.
    float p0 = h * W_cls[f];
    float p1 = h * W_cls[FF + f];
    #pragma unroll
    for (int off = 16; off > 0; off >>= 1) {
        p0 += __shfl_down_sync(0xFFFFFFFFu, p0, off);
        p1 += __shfl_down_sync(0xFFFFFFFFu, p1, off);
    }
    __shared__ float w0[FF / 32], w1[FF / 32];
    const int warp = f >> 5, lane = f & 31;
    if (lane == 0) { w0[warp] = p0; w1[warp] = p1; }
    __syncthreads();
    if (f == 0) {
        float l0 = b_cls[0], l1 = b_cls[1];
        #pragma unroll
        for (int w = 0; w < FF / 32; w++) { l0 += w0[w]; l1 += w1[w]; }
        out[b * 2 + 0] = 1.0f / (1.0f + __expf(-l0));
        out[b * 2 + 1] = 1.0f / (1.0f + __expf(-l1));
    }
}

extern "C" void kernel_launch(void* const* d_in, const int* in_sizes, int n_in,
                              void* d_out, int out_size)
{
    grud_kernel<<<BB, FF>>>(
        (const float*)d_in[0],  // input
        (const float*)d_in[1],  // x_mean
        (const float*)d_in[2],  // w_xz
        (const float*)d_in[3],  // w_hz
        (const float*)d_in[4],  // w_mz
        (const float*)d_in[5],  // w_xr
        (const float*)d_in[6],  // w_hr
        (const float*)d_in[7],  // w_mr
        (const float*)d_in[8],  // w_xh
        (const float*)d_in[9],  // w_hh
        (const float*)d_in[10], // w_mh
        (const float*)d_in[11], // b_z
        (const float*)d_in[12], // b_r
        (const float*)d_in[13], // b_h
        (const float*)d_in[14], // W_cls
        (const float*)d_in[15], // b_cls
        (float*)d_out);
}

// round 3
// speedup vs baseline: 1.3336x; 1.3336x over previous
#include <cuda_runtime.h>

// GRU-D with diagonal weights: 32,768 independent scalar recurrences,
// one thread per (b,f); block = one batch row; fused classifier.
//
// Shapes (fixed): B=128, T=1024, F=256, OUT=2.
// input: (B, 3, T, F) float32 -> channel 0 = X, 1 = M, 2 = D (unused).
//
// R3 change: UNR=16 + statically-unrolled two-phase double buffer so the
// prefetch distance (~768 cyc of compute) exceeds loaded-DRAM latency,
// and __ldcs streaming loads. Target: lift HBM from 1.93 TB/s toward 6.

#define BB   128
#define TT   1024
#define FF   256
#define UNR  16

__device__ __forceinline__ float tanh_fast(float x) {
    float y;
    asm("tanh.approx.f32 %0, %1;" : "=f"(y) : "f"(x));
    return y;
}

struct GruConsts {
    float xm;
    float hwxz, hwmz, hbz, hwhz;
    float hwxr, hwmr, hbr, hwhr;
    float wxh, wmh, bh, hwhh;
};

__device__ __forceinline__ float gru_step(float h, float x, float m,
                                          const GruConsts& c) {
    // Imputation: m*x + (1-m)*x_mean == fma(m, x - xm, xm)
    const float xi  = fmaf(m, x - c.xm, c.xm);
    // h-independent pre-activations (off the critical chain)
    const float azh = fmaf(c.hwxz, xi, fmaf(c.hwmz, m, c.hbz));
    const float arh = fmaf(c.hwxr, xi, fmaf(c.hwmr, m, c.hbr));
    const float ah  = fmaf(c.wxh,  xi, fmaf(c.wmh,  m, c.bh ));
    const float g   = c.hwhh * h;                  // 0.5*w_hh*h
    // sigmoid(y) = 0.5*tanh(0.5*y)+0.5 with 0.5 folded into weights
    const float tz  = tanh_fast(fmaf(c.hwhz, h, azh));
    const float tr  = tanh_fast(fmaf(c.hwhr, h, arh));
    const float z   = fmaf(0.5f, tz, 0.5f);
    // w_hh*(r*h) = g*tr + g   since r = 0.5*tr + 0.5
    const float th  = tanh_fast(fmaf(g, tr, g + ah));
    return fmaf(z, th - h, h);                     // (1-z)h + z*h~
}

__global__ __launch_bounds__(FF, 1)
void grud_kernel(const float* __restrict__ input,
                 const float* __restrict__ x_mean,
                 const float* __restrict__ w_xz, const float* __restrict__ w_hz,
                 const float* __restrict__ w_mz,
                 const float* __restrict__ w_xr, const float* __restrict__ w_hr,
                 const float* __restrict__ w_mr,
                 const float* __restrict__ w_xh, const float* __restrict__ w_hh,
                 const float* __restrict__ w_mh,
                 const float* __restrict__ b_z,  const float* __restrict__ b_r,
                 const float* __restrict__ b_h,
                 const float* __restrict__ W_cls, const float* __restrict__ b_cls,
                 float* __restrict__ out)
{
    const int b = blockIdx.x;
    const int f = threadIdx.x;

    GruConsts c;
    c.xm   = x_mean[f];
    c.hwxz = 0.5f * w_xz[f]; c.hwmz = 0.5f * w_mz[f];
    c.hbz  = 0.5f * b_z[f];  c.hwhz = 0.5f * w_hz[f];
    c.hwxr = 0.5f * w_xr[f]; c.hwmr = 0.5f * w_mr[f];
    c.hbr  = 0.5f * b_r[f];  c.hwhr = 0.5f * w_hr[f];
    c.wxh  = w_xh[f]; c.wmh = w_mh[f]; c.bh = b_h[f];
    c.hwhh = 0.5f * w_hh[f];

    const float* xp = input + (size_t)b * 3 * TT * FF + f;   // X[b, t, f]
    const float* mp = xp + (size_t)TT * FF;                  // M[b, t, f]

    float h = 0.0f;

    // Two statically-named buffers; phases alternate with compile-time roles.
    float xa[UNR], ma[UNR], xb2[UNR], mb2[UNR];

    // Prologue: load steps 0..UNR-1 into A.
    #pragma unroll
    for (int u = 0; u < UNR; u++) {
        xa[u] = __ldcs(xp + u * FF);
        ma[u] = __ldcs(mp + u * FF);
    }

    // Each outer iteration covers 2*UNR steps. TT % (2*UNR) == 0.
    for (int t = 0; t < TT; t += 2 * UNR) {
        // Phase 1: prefetch B = steps [t+UNR, t+2*UNR)  (always in range),
        // then compute A.
        const float* xq = xp + (t + UNR) * FF;
        const float* mq = mp + (t + UNR) * FF;
        #pragma unroll
        for (int u = 0; u < UNR; u++) {
            xb2[u] = __ldcs(xq + u * FF);
            mb2[u] = __ldcs(mq + u * FF);
        }
        #pragma unroll
        for (int u = 0; u < UNR; u++)
            h = gru_step(h, xa[u], ma[u], c);

        // Phase 2: prefetch A = steps [t+2*UNR, t+3*UNR) (skip on last iter),
        // then compute B.
        if (t + 2 * UNR < TT) {
            const float* xr = xp + (t + 2 * UNR) * FF;
            const float* mr = mp + (t + 2 * UNR) * FF;
            #pragma unroll
            for (int u = 0; u < UNR; u++) {
                xa[u] = __ldcs(xr + u * FF);
                ma[u] = __ldcs(mr + u * FF);
            }
        }
        #pragma unroll
        for (int u = 0; u < UNR; u++)
            h = gru_step(h, xb2[u], mb2[u], c);
    }

    // Fused classifier: out[b, o] = sigmoid(sum_f h*W_cls[o,f] + b_cls[o])
    float p0 = h * W_cls[f];
    float p1 = h * W_cls[FF + f];
    #pragma unroll
    for (int off = 16; off > 0; off >>= 1) {
        p0 += __shfl_down_sync(0xFFFFFFFFu, p0, off);
        p1 += __shfl_down_sync(0xFFFFFFFFu, p1, off);
    }
    __shared__ float w0[FF / 32], w1[FF / 32];
    const int warp = f >> 5, lane = f & 31;
    if (lane == 0) { w0[warp] = p0; w1[warp] = p1; }
    __syncthreads();
    if (f == 0) {
        float l0 = b_cls[0], l1 = b_cls[1];
        #pragma unroll
        for (int w = 0; w < FF / 32; w++) { l0 += w0[w]; l1 += w1[w]; }
        out[b * 2 + 0] = 1.0f / (1.0f + __expf(-l0));
        out[b * 2 + 1] = 1.0f / (1.0f + __expf(-l1));
    }
}

extern "C" void kernel_launch(void* const* d_in, const int* in_sizes, int n_in,
                              void* d_out, int out_size)
{
    grud_kernel<<<BB, FF>>>(
        (const float*)d_in[0],  // input
        (const float*)d_in[1],  // x_mean
        (const float*)d_in[2],  // w_xz
        (const float*)d_in[3],  // w_hz
        (const float*)d_in[4],  // w_mz
        (const float*)d_in[5],  // w_xr
        (const float*)d_in[6],  // w_hr
        (const float*)d_in[7],  // w_mr
        (const float*)d_in[8],  // w_xh
        (const float*)d_in[9],  // w_hh
        (const float*)d_in[10], // w_mh
        (const float*)d_in[11], // b_z
        (const float*)d_in[12], // b_r
        (const float*)d_in[13], // b_h
        (const float*)d_in[14], // W_cls
        (const float*)d_in[15], // b_cls
        (float*)d_out);
}